// round 1
// baseline (speedup 1.0000x reference)
#include <cuda_runtime.h>

#define NT 8192
#define DD 1024
#define UU 512
#define EE 8

// ---- scratch (static device globals; no runtime allocation) ----
__device__ int   g_count[EE];
__device__ int   g_off[EE];
__device__ int   g_list[EE * NT];
__device__ float g_H[NT * UU];          // 16 MB compact hidden activations

// ---------------------------------------------------------------
__global__ void k_zero() {
    if (threadIdx.x < EE) g_count[threadIdx.x] = 0;
}

// warp-per-token gating: logits = x@Wg + bg, argmax -> append to expert list
__global__ void k_gate(const float* __restrict__ x,
                       const float* __restrict__ Wg,
                       const float* __restrict__ bg) {
    int warp = (blockIdx.x * blockDim.x + threadIdx.x) >> 5;
    int lane = threadIdx.x & 31;
    if (warp >= NT) return;
    const float* xr = x + (size_t)warp * DD;
    float acc[EE];
#pragma unroll
    for (int e = 0; e < EE; e++) acc[e] = 0.f;
    for (int d = lane; d < DD; d += 32) {
        float xv = xr[d];
        const float4* wr = (const float4*)(Wg + d * EE);
        float4 w0 = wr[0], w1 = wr[1];
        acc[0] += xv * w0.x; acc[1] += xv * w0.y;
        acc[2] += xv * w0.z; acc[3] += xv * w0.w;
        acc[4] += xv * w1.x; acc[5] += xv * w1.y;
        acc[6] += xv * w1.z; acc[7] += xv * w1.w;
    }
#pragma unroll
    for (int e = 0; e < EE; e++) {
#pragma unroll
        for (int off = 16; off; off >>= 1)
            acc[e] += __shfl_xor_sync(0xffffffffu, acc[e], off);
    }
    if (lane == 0) {
        int best = 0;
        float bv = acc[0] + bg[0];
#pragma unroll
        for (int e = 1; e < EE; e++) {
            float v = acc[e] + bg[e];
            if (v > bv) { bv = v; best = e; }   // strict > : first max wins (matches jnp.argmax)
        }
        int pos = atomicAdd(&g_count[best], 1);
        g_list[best * NT + pos] = warp;
    }
}

__global__ void k_offs() {
    if (threadIdx.x == 0) {
        int s = 0;
#pragma unroll
        for (int e = 0; e < EE; e++) { g_off[e] = s; s += g_count[e]; }
    }
}

// ---------------------------------------------------------------
// GEMM1: H = swish(gather(X) @ W1[e] + b1[e]),  [cnt x 1024] @ [1024 x 512]
// tile 128x128, BK=16, 256 threads, 8x8 microtile
__global__ __launch_bounds__(256, 2)
void k_fc1(const float* __restrict__ x,
           const float* __restrict__ W1,
           const float* __restrict__ b1) {
    const int e   = blockIdx.z;
    const int cnt = g_count[e];
    const int m0  = blockIdx.y * 128;
    if (m0 >= cnt) return;
    const int n0   = blockIdx.x * 128;
    const int base = g_off[e];

    __shared__ float As[16][132];
    __shared__ float Bs[16][132];
    __shared__ int   sRow[128];

    const int tid = threadIdx.x;
    if (tid < 128) {
        int m = m0 + tid;
        sRow[tid] = g_list[e * NT + (m < cnt ? m : cnt - 1)];
    }
    __syncthreads();

    const int r0 = tid >> 2;           // 0..63
    const int c4 = (tid & 3) * 4;      // 0,4,8,12
    const float* aP0 = x + (size_t)sRow[r0]      * DD + c4;
    const float* aP1 = x + (size_t)sRow[r0 + 64] * DD + c4;
    const int br = tid >> 5;           // 0..7
    const int bc = (tid & 31) * 4;
    const float* bP = W1 + (size_t)e * DD * UU + (size_t)br * UU + n0 + bc;

    const int tx = tid & 15, ty = tid >> 4;
    float acc[8][8];
#pragma unroll
    for (int i = 0; i < 8; i++)
#pragma unroll
        for (int j = 0; j < 8; j++) acc[i][j] = 0.f;

    for (int k0 = 0; k0 < DD; k0 += 16) {
        float4 a0 = *(const float4*)(aP0 + k0);
        float4 a1 = *(const float4*)(aP1 + k0);
        float4 b0 = *(const float4*)(bP + (size_t)k0 * UU);
        float4 b1v = *(const float4*)(bP + (size_t)(k0 + 8) * UU);
        As[c4 + 0][r0] = a0.x; As[c4 + 1][r0] = a0.y;
        As[c4 + 2][r0] = a0.z; As[c4 + 3][r0] = a0.w;
        As[c4 + 0][r0 + 64] = a1.x; As[c4 + 1][r0 + 64] = a1.y;
        As[c4 + 2][r0 + 64] = a1.z; As[c4 + 3][r0 + 64] = a1.w;
        *(float4*)&Bs[br][bc]     = b0;
        *(float4*)&Bs[br + 8][bc] = b1v;
        __syncthreads();
#pragma unroll
        for (int kk = 0; kk < 16; kk++) {
            float a[8], b[8];
            *(float4*)(a)     = *(float4*)&As[kk][ty * 8];
            *(float4*)(a + 4) = *(float4*)&As[kk][ty * 8 + 4];
            *(float4*)(b)     = *(float4*)&Bs[kk][tx * 8];
            *(float4*)(b + 4) = *(float4*)&Bs[kk][tx * 8 + 4];
#pragma unroll
            for (int i = 0; i < 8; i++)
#pragma unroll
                for (int j = 0; j < 8; j++)
                    acc[i][j] += a[i] * b[j];
        }
        __syncthreads();
    }

    // epilogue: bias + swish -> compact H
    float bias[8];
#pragma unroll
    for (int j = 0; j < 8; j++) bias[j] = b1[e * UU + n0 + tx * 8 + j];
#pragma unroll
    for (int i = 0; i < 8; i++) {
        int m = m0 + ty * 8 + i;
        if (m < cnt) {
            float* Hr = g_H + (size_t)(base + m) * UU + n0 + tx * 8;
#pragma unroll
            for (int j = 0; j < 8; j++) {
                float t = acc[i][j] + bias[j];
                Hr[j] = t * __fdividef(1.f, 1.f + __expf(-t));
            }
        }
    }
}

// ---------------------------------------------------------------
// GEMM2: Z = H @ proj[e], fused sigmoid + RBF spline + ctrl contraction,
// scattered write to out[token]
__global__ __launch_bounds__(256, 2)
void k_fc2(const float* __restrict__ proj,
           const float* __restrict__ ctrl,
           const float* __restrict__ scaling,
           float* __restrict__ out) {
    const int e   = blockIdx.z;
    const int cnt = g_count[e];
    const int m0  = blockIdx.y * 128;
    if (m0 >= cnt) return;
    const int n0   = blockIdx.x * 128;
    const int base = g_off[e];

    __shared__ float As[16][132];
    __shared__ float Bs[16][132];
    __shared__ int   sRow[128];
    __shared__ float sCtrl[8][128];
    __shared__ float sScal[128];

    const int tid = threadIdx.x;
    if (tid < 128) {
        int m = m0 + tid;
        sRow[tid] = g_list[e * NT + (m < cnt ? m : cnt - 1)];
        sScal[tid] = scaling[e * UU + n0 + tid];
    }
    {   // ctrl slice: [8][128] = 256 float4 loads
        int b = tid >> 5, c = (tid & 31) * 4;
        *(float4*)&sCtrl[b][c] = *(const float4*)(ctrl + (size_t)e * 8 * UU + (size_t)b * UU + n0 + c);
    }
    __syncthreads();

    const int r0 = tid >> 2;
    const int c4 = (tid & 3) * 4;
    int mr0 = m0 + r0;      if (mr0 >= cnt)  mr0 = cnt - 1;
    int mr1 = m0 + r0 + 64; if (mr1 >= cnt)  mr1 = cnt - 1;
    const float* aP0 = g_H + (size_t)(base + mr0) * UU + c4;
    const float* aP1 = g_H + (size_t)(base + mr1) * UU + c4;
    const int br = tid >> 5;
    const int bc = (tid & 31) * 4;
    const float* bP = proj + (size_t)e * UU * UU + (size_t)br * UU + n0 + bc;

    const int tx = tid & 15, ty = tid >> 4;
    float acc[8][8];
#pragma unroll
    for (int i = 0; i < 8; i++)
#pragma unroll
        for (int j = 0; j < 8; j++) acc[i][j] = 0.f;

    for (int k0 = 0; k0 < UU; k0 += 16) {
        float4 a0 = *(const float4*)(aP0 + k0);
        float4 a1 = *(const float4*)(aP1 + k0);
        float4 b0 = *(const float4*)(bP + (size_t)k0 * UU);
        float4 b1v = *(const float4*)(bP + (size_t)(k0 + 8) * UU);
        As[c4 + 0][r0] = a0.x; As[c4 + 1][r0] = a0.y;
        As[c4 + 2][r0] = a0.z; As[c4 + 3][r0] = a0.w;
        As[c4 + 0][r0 + 64] = a1.x; As[c4 + 1][r0 + 64] = a1.y;
        As[c4 + 2][r0 + 64] = a1.z; As[c4 + 3][r0 + 64] = a1.w;
        *(float4*)&Bs[br][bc]     = b0;
        *(float4*)&Bs[br + 8][bc] = b1v;
        __syncthreads();
#pragma unroll
        for (int kk = 0; kk < 16; kk++) {
            float a[8], b[8];
            *(float4*)(a)     = *(float4*)&As[kk][ty * 8];
            *(float4*)(a + 4) = *(float4*)&As[kk][ty * 8 + 4];
            *(float4*)(b)     = *(float4*)&Bs[kk][tx * 8];
            *(float4*)(b + 4) = *(float4*)&Bs[kk][tx * 8 + 4];
#pragma unroll
            for (int i = 0; i < 8; i++)
#pragma unroll
                for (int j = 0; j < 8; j++)
                    acc[i][j] += a[i] * b[j];
        }
        __syncthreads();
    }

    // epilogue: sigmoid -> gaussian-RBF basis over 8 knots -> ctrl dot -> scale -> scatter
#pragma unroll
    for (int i = 0; i < 8; i++) {
        int m = m0 + ty * 8 + i;
        if (m < cnt) {
            int tok = sRow[ty * 8 + i];
            float* orow = out + (size_t)tok * UU + n0 + tx * 8;
#pragma unroll
            for (int j = 0; j < 8; j++) {
                float z  = acc[i][j];
                float xn = __fdividef(1.f, 1.f + __expf(-z));
                float s = 1e-6f, num = 0.f;
#pragma unroll
                for (int b = 0; b < 8; b++) {
                    float d = xn - (float)b * (1.0f / 7.0f);
                    float w = __expf(-32.f * d * d);   // exp(-dist / (2*(1/8)^2))
                    s   += w;
                    num += w * sCtrl[b][tx * 8 + j];
                }
                orow[j] = __fdividef(num, s) * sScal[tx * 8 + j];
            }
        }
    }
}

// ---------------------------------------------------------------
extern "C" void kernel_launch(void* const* d_in, const int* in_sizes, int n_in,
                              void* d_out, int out_size) {
    const float* x       = (const float*)d_in[0];
    const float* W1      = (const float*)d_in[1];
    const float* b1      = (const float*)d_in[2];
    const float* proj    = (const float*)d_in[3];
    const float* ctrl    = (const float*)d_in[4];
    const float* scaling = (const float*)d_in[5];
    const float* Wg      = (const float*)d_in[6];
    const float* bg      = (const float*)d_in[7];
    float* out = (float*)d_out;

    k_zero<<<1, 32>>>();
    k_gate<<<NT / 8, 256>>>(x, Wg, bg);
    k_offs<<<1, 1>>>();
    dim3 grid(UU / 128, NT / 128, EE);
    k_fc1<<<grid, 256>>>(x, W1, b1);
    k_fc2<<<grid, 256>>>(proj, ctrl, scaling, out);
}

// round 7
// speedup vs baseline: 1.0849x; 1.0849x over previous
#include <cuda_runtime.h>
#include <cstdint>

#define NT 8192
#define DD 1024
#define UU 512
#define EE 8

// ---------------- helpers ----------------
__device__ __forceinline__ uint32_t smem_to_u32(const void* p) {
    uint32_t a;
    asm("{ .reg .u64 t; cvta.to.shared.u64 t, %1; cvt.u32.u64 %0, t; }" : "=r"(a) : "l"(p));
    return a;
}
__device__ __forceinline__ uint32_t f2tf32(float v) {
    uint32_t r; asm("cvt.rna.tf32.f32 %0, %1;" : "=r"(r) : "f"(v)); return r;
}
__device__ __forceinline__ void mma8(float* c, const uint32_t* a, const uint32_t* b) {
    asm volatile(
        "mma.sync.aligned.m16n8k8.row.col.f32.tf32.tf32.f32 "
        "{%0,%1,%2,%3}, {%4,%5,%6,%7}, {%8,%9}, {%0,%1,%2,%3};"
        : "+f"(c[0]), "+f"(c[1]), "+f"(c[2]), "+f"(c[3])
        : "r"(a[0]), "r"(a[1]), "r"(a[2]), "r"(a[3]), "r"(b[0]), "r"(b[1]));
}
#define CP_ASYNC16(dst, src) \
    asm volatile("cp.async.cg.shared.global [%0], [%1], 16;" :: "r"(dst), "l"(src))
#define CP_COMMIT() asm volatile("cp.async.commit_group;" ::: "memory")
#define CP_WAIT0()  asm volatile("cp.async.wait_group 0;" ::: "memory")

// ---------------- scratch (device globals only; no host symbol queries) ----------------
__device__ int   g_count[EE];
__device__ int   g_off[EE];
__device__ int   g_list[EE * NT];
__device__ float g_H[NT * UU];                 // 16 MB compact hidden

// ---------------- small kernels (R1-proven forms) ----------------
__global__ void k_zero() { if (threadIdx.x < EE) g_count[threadIdx.x] = 0; }

__global__ void k_gate(const float* __restrict__ x,
                       const float* __restrict__ Wg,
                       const float* __restrict__ bg) {
    int warp = (blockIdx.x * blockDim.x + threadIdx.x) >> 5;
    int lane = threadIdx.x & 31;
    if (warp >= NT) return;
    const float* xr = x + (size_t)warp * DD;
    float acc[EE];
#pragma unroll
    for (int e = 0; e < EE; e++) acc[e] = 0.f;
    for (int d = lane; d < DD; d += 32) {
        float xv = xr[d];
        const float4* wr = (const float4*)(Wg + d * EE);
        float4 w0 = wr[0], w1 = wr[1];
        acc[0] += xv * w0.x; acc[1] += xv * w0.y;
        acc[2] += xv * w0.z; acc[3] += xv * w0.w;
        acc[4] += xv * w1.x; acc[5] += xv * w1.y;
        acc[6] += xv * w1.z; acc[7] += xv * w1.w;
    }
#pragma unroll
    for (int e = 0; e < EE; e++)
#pragma unroll
        for (int off = 16; off; off >>= 1)
            acc[e] += __shfl_xor_sync(0xffffffffu, acc[e], off);
    if (lane == 0) {
        int best = 0; float bv = acc[0] + bg[0];
#pragma unroll
        for (int e = 1; e < EE; e++) {
            float v = acc[e] + bg[e];
            if (v > bv) { bv = v; best = e; }
        }
        int pos = atomicAdd(&g_count[best], 1);
        g_list[best * NT + pos] = warp;
    }
}

__global__ void k_offs() {
    if (threadIdx.x == 0) {
        int s = 0;
#pragma unroll
        for (int e = 0; e < EE; e++) { g_off[e] = s; s += g_count[e]; }
    }
}

// ---------------- mma.sync tf32 (3x split) GEMM ----------------
// CTA tile 128x64, 256 threads, 8 warps (4m x 2n), warp tile 32x32.
// B staged K-major in SMEM (matches W1/proj layout directly -> no transpose).
template<int KK, bool FC2>
__global__ __launch_bounds__(256)
void k_gemm(const float* __restrict__ Asrc,    // x (fc1) / unused (fc2)
            const float* __restrict__ Bsrc,    // W1[e] base / proj[e] base handled via e
            const float* __restrict__ aux1,    // b1 (fc1) / ctrl (fc2)
            const float* __restrict__ aux2,    // unused  / scaling
            float* __restrict__ out)           // unused (fc1 writes g_H) / d_out
{
    __shared__ float As[2][128][20];   // [stage][m][k]
    __shared__ float Bs[2][16][72];    // [stage][k][n], pad 72 -> conflict-free
    __shared__ int   sRow[128];
    __shared__ float sBias[64];
    __shared__ float sCtrl[8][64];

    const int tid = threadIdx.x, wid = tid >> 5, lane = tid & 31;
    const int g = lane >> 2, tg = lane & 3;
    const int e = blockIdx.z;
    const int cnt = g_count[e];
    const int m0 = blockIdx.y * 128;
    if (m0 >= cnt) return;
    const int n0 = blockIdx.x * 64;
    const int base = g_off[e];

    if (tid < 128) {
        int m = m0 + tid;
        sRow[tid] = g_list[e * NT + (m < cnt ? m : cnt - 1)];
    }
    if (tid < 64)
        sBias[tid] = FC2 ? aux2[e * UU + n0 + tid] : aux1[e * UU + n0 + tid];
    if (FC2 && tid < 128) {
        int b = tid >> 4, c = (tid & 15) * 4;
        *(float4*)&sCtrl[b][c] =
            *(const float4*)(aux1 + (size_t)e * 8 * UU + (size_t)b * UU + n0 + c);
    }
    __syncthreads();

    // ---- copy assignments ----
    // A: 128 rows x 16 k = 512 float4 -> 2 per thread
    const int ra0 = tid >> 2, ca = (tid & 3) * 4;      // rows ra0, ra0+64
    const float* gA0; const float* gA1;
    if (FC2) {
        int mA0 = m0 + ra0;      if (mA0 >= cnt) mA0 = cnt - 1;
        int mA1 = m0 + ra0 + 64; if (mA1 >= cnt) mA1 = cnt - 1;
        gA0 = g_H + (size_t)(base + mA0) * UU + ca;
        gA1 = g_H + (size_t)(base + mA1) * UU + ca;
    } else {
        gA0 = Asrc + (size_t)sRow[ra0] * DD + ca;
        gA1 = Asrc + (size_t)sRow[ra0 + 64] * DD + ca;
    }
    const uint32_t sA0 = (uint32_t)(ra0 * 20 + ca) * 4;
    const uint32_t sA1 = (uint32_t)((ra0 + 64) * 20 + ca) * 4;
    // B: 16 k-rows x 64 n = 256 float4 -> 1 per thread
    const int rb = tid >> 4, cb = (tid & 15) * 4;
    const float* Bexp = Bsrc + (size_t)e * UU * KK;    // [k][n] layout, row stride UU
    const float* gB = Bexp + (size_t)rb * UU + n0 + cb;
    const uint32_t sB = (uint32_t)(rb * 72 + cb) * 4;

    const uint32_t asU = smem_to_u32(As), bsU = smem_to_u32(Bs);
    const uint32_t A_STG = 128 * 20 * 4, B_STG = 16 * 72 * 4;

    const int m_base = (wid >> 1) * 32;
    const int n_base = (wid & 1) * 32;

    float acc[2][4][4];
#pragma unroll
    for (int mi = 0; mi < 2; mi++)
#pragma unroll
        for (int ni = 0; ni < 4; ni++)
#pragma unroll
            for (int q = 0; q < 4; q++) acc[mi][ni][q] = 0.f;

    const int NCH = KK / 16;
    CP_ASYNC16(asU + sA0, gA0);
    CP_ASYNC16(asU + sA1, gA1);
    CP_ASYNC16(bsU + sB, gB);
    CP_COMMIT();

    for (int ch = 0; ch < NCH; ch++) {
        CP_WAIT0();
        __syncthreads();
        if (ch + 1 < NCH) {
            const int k0 = (ch + 1) * 16;
            const uint32_t st = ((ch + 1) & 1);
            CP_ASYNC16(asU + st * A_STG + sA0, gA0 + k0);
            CP_ASYNC16(asU + st * A_STG + sA1, gA1 + k0);
            CP_ASYNC16(bsU + st * B_STG + sB, gB + (size_t)k0 * UU);
            CP_COMMIT();
        }
        const int p = ch & 1;
#pragma unroll
        for (int ks = 0; ks < 2; ks++) {
            const int k = ks * 8;
            uint32_t bh[4][2], bl[4][2];
#pragma unroll
            for (int ni = 0; ni < 4; ni++) {
                const int col = n_base + ni * 8 + g;
                float u0 = Bs[p][k + tg][col];
                float u1 = Bs[p][k + tg + 4][col];
                bh[ni][0] = f2tf32(u0); bl[ni][0] = f2tf32(u0 - __uint_as_float(bh[ni][0]));
                bh[ni][1] = f2tf32(u1); bl[ni][1] = f2tf32(u1 - __uint_as_float(bh[ni][1]));
            }
#pragma unroll
            for (int mi = 0; mi < 2; mi++) {
                const int r0 = m_base + mi * 16 + g;
                float v0 = As[p][r0][k + tg];
                float v1 = As[p][r0 + 8][k + tg];
                float v2 = As[p][r0][k + tg + 4];
                float v3 = As[p][r0 + 8][k + tg + 4];
                uint32_t ah[4], al[4];
                ah[0] = f2tf32(v0); al[0] = f2tf32(v0 - __uint_as_float(ah[0]));
                ah[1] = f2tf32(v1); al[1] = f2tf32(v1 - __uint_as_float(ah[1]));
                ah[2] = f2tf32(v2); al[2] = f2tf32(v2 - __uint_as_float(ah[2]));
                ah[3] = f2tf32(v3); al[3] = f2tf32(v3 - __uint_as_float(ah[3]));
#pragma unroll
                for (int ni = 0; ni < 4; ni++) {
                    mma8(acc[mi][ni], ah, bh[ni]);
                    mma8(acc[mi][ni], ah, bl[ni]);
                    mma8(acc[mi][ni], al, bh[ni]);
                }
            }
        }
        __syncthreads();
    }

    // ---------------- epilogue ----------------
#pragma unroll
    for (int mi = 0; mi < 2; mi++) {
#pragma unroll
        for (int half = 0; half < 2; half++) {
            const int rloc = m_base + mi * 16 + g + half * 8;
            const int m = m0 + rloc;
            if (m >= cnt) continue;
            float* dstRow;
            if (FC2) dstRow = out + (size_t)sRow[rloc] * UU + n0;
            else     dstRow = g_H + (size_t)(base + m) * UU + n0;
#pragma unroll
            for (int ni = 0; ni < 4; ni++) {
                const int cl = n_base + ni * 8 + 2 * tg;
                float z0 = acc[mi][ni][half * 2 + 0];
                float z1 = acc[mi][ni][half * 2 + 1];
                float2 v;
                if (!FC2) {
                    float t0 = z0 + sBias[cl], t1 = z1 + sBias[cl + 1];
                    v.x = t0 * __fdividef(1.f, 1.f + __expf(-t0));
                    v.y = t1 * __fdividef(1.f, 1.f + __expf(-t1));
                } else {
#pragma unroll
                    for (int q = 0; q < 2; q++) {
                        float z = q ? z1 : z0;
                        float xn = __fdividef(1.f, 1.f + __expf(-z));
                        float s = 1e-6f, num = 0.f;
#pragma unroll
                        for (int b = 0; b < 8; b++) {
                            float d = xn - (float)b * (1.0f / 7.0f);
                            float w = __expf(-32.f * d * d);
                            s += w;
                            num += w * sCtrl[b][cl + q];
                        }
                        float r = __fdividef(num, s) * sBias[cl + q];
                        if (q) v.y = r; else v.x = r;
                    }
                }
                *(float2*)(dstRow + cl) = v;
            }
        }
    }
}

// ---------------- launch (kernel launches ONLY — no other CUDA API) ----------------
extern "C" void kernel_launch(void* const* d_in, const int* in_sizes, int n_in,
                              void* d_out, int out_size) {
    const float* x       = (const float*)d_in[0];
    const float* W1      = (const float*)d_in[1];
    const float* b1      = (const float*)d_in[2];
    const float* proj    = (const float*)d_in[3];
    const float* ctrl    = (const float*)d_in[4];
    const float* scaling = (const float*)d_in[5];
    const float* Wg      = (const float*)d_in[6];
    const float* bg      = (const float*)d_in[7];
    float* out = (float*)d_out;

    k_zero<<<1, 32>>>();
    k_gate<<<NT / 8, 256>>>(x, Wg, bg);
    k_offs<<<1, 1>>>();
    dim3 grid(UU / 64, NT / 128, EE);
    k_gemm<DD, false><<<grid, 256>>>(x, W1, b1, nullptr, out);
    k_gemm<UU, true><<<grid, 256>>>(nullptr, proj, ctrl, scaling, out);
}